// round 15
// baseline (speedup 1.0000x reference)
#include <cuda_runtime.h>
#include <math.h>
#include <stdint.h>

// ContrastiveLoss fused via warp-level FP8(e4m3) mma.sync (m16n8k32).
// 128x64 CTA tiles (8 warps of 32x32), 3 CTAs/SM for occupancy.
// Strip-major persistent CTAs, A resident per strip (double-buffered),
// B double-buffered, smem-staged row sums flushed at strip/mode boundaries,
// warp-level no-match skip, in-kernel loss tail.
// Inputs: x [M,D] f32, track_idxs [M] i32, y [n,Q,D] f32. Output: scalar f32.

#define MAX_M  8192
#define DK     128
#define TILE   128            // M tile (strip height)
#define NT     64             // N tile
#define ASTRB  144            // padded row stride in bytes
#define NPCTA  444            // 3 per SM x 148

// smem layout (bytes)
#define GA0    0              // A buf0 128x144 = 18432
#define GA1    18432
#define GB0    36864          // B buf0 64x144 = 9216
#define GB1    46080
#define GTRS   55296          // 2 x 512 row labels
#define GTCS   56320          // 2 x 256 col labels
#define GRS    56832          // 2 slices x 128 f32 row sums
#define GSS    57856          // 2 slices x 128 f32 same-track sums
#define SM_TOTAL 58880

__device__ uint8_t g_xa[(size_t)MAX_M * DK];       // x * log2(e)/T, e4m3 (A)
__device__ uint8_t g_x8[(size_t)MAX_M * DK];       // x, e4m3 (B, xx)
__device__ uint8_t g_y8[(size_t)MAX_M * DK / 2];   // y, e4m3 (B, xy)
__device__ double g_A[MAX_M];
__device__ double g_P[MAX_M];
__device__ double g_RT[MAX_M];
__device__ double g_G[MAX_M];
__device__ double g_DS[MAX_M];
__device__ int    g_n = 0;
__device__ int    g_done = 0;

__device__ __forceinline__ uint32_t smem_u32(const void* p) {
    uint32_t a;
    asm("{ .reg .u64 t; cvta.to.shared.u64 t, %1; cvt.u32.u64 %0, t; }" : "=r"(a) : "l"(p));
    return a;
}
__device__ __forceinline__ float ex2f(float x) {
    float r; asm("ex2.approx.f32 %0, %1;" : "=f"(r) : "f"(x)); return r;
}
__device__ __forceinline__ void ldmx4(uint32_t* r, uint32_t addr) {
    asm volatile("ldmatrix.sync.aligned.m8n8.x4.shared.b16 {%0,%1,%2,%3}, [%4];"
                 : "=r"(r[0]), "=r"(r[1]), "=r"(r[2]), "=r"(r[3]) : "r"(addr));
}
__device__ __forceinline__ void mma16832(float* d, const uint32_t* a, uint32_t b0, uint32_t b1) {
    asm volatile("mma.sync.aligned.m16n8k32.row.col.f32.e4m3.e4m3.f32 "
                 "{%0,%1,%2,%3}, {%4,%5,%6,%7}, {%8,%9}, {%0,%1,%2,%3};"
                 : "+f"(d[0]), "+f"(d[1]), "+f"(d[2]), "+f"(d[3])
                 : "r"(a[0]), "r"(a[1]), "r"(a[2]), "r"(a[3]), "r"(b0), "r"(b1));
}
__device__ __forceinline__ void cpasync16(uint32_t saddr, const void* gptr) {
    asm volatile("cp.async.cg.shared.global [%0], [%1], 16;" :: "r"(saddr), "l"(gptr));
}
__device__ __forceinline__ uint32_t pack_e4m3_4(float a, float b, float c, float d) {
    uint16_t lo, hi;
    asm("cvt.rn.satfinite.e4m3x2.f32 %0, %1, %2;" : "=h"(lo) : "f"(b), "f"(a));
    asm("cvt.rn.satfinite.e4m3x2.f32 %0, %1, %2;" : "=h"(hi) : "f"(d), "f"(c));
    return (uint32_t)lo | ((uint32_t)hi << 16);
}

// ---------------------------------------------------------------------------
__global__ void k_prep(const float* __restrict__ x, const float* __restrict__ y,
                       const int* __restrict__ trk, int M, int nQ) {
    const float S = 1.4426950408889634f / 0.3f;   // log2(e)/TEMP
    int t = blockIdx.x * blockDim.x + threadIdx.x;
    int nx4 = M * DK / 4;
    int ny4 = nQ * DK / 4;
    if (t < nx4) {
        float4 v = *reinterpret_cast<const float4*>(x + t * 4);
        *reinterpret_cast<uint32_t*>(g_xa + t * 4) =
            pack_e4m3_4(v.x * S, v.y * S, v.z * S, v.w * S);
        *reinterpret_cast<uint32_t*>(g_x8 + t * 4) = pack_e4m3_4(v.x, v.y, v.z, v.w);
    } else if (t < nx4 + ny4) {
        int i = t - nx4;
        float4 v = *reinterpret_cast<const float4*>(y + i * 4);
        *reinterpret_cast<uint32_t*>(g_y8 + i * 4) = pack_e4m3_4(v.x, v.y, v.z, v.w);
    }
    if (t < MAX_M) { g_A[t] = 0; g_P[t] = 0; g_RT[t] = 0; g_G[t] = 0; g_DS[t] = 0; }
    if (t == 0) g_done = 0;
    if (t < M) atomicMax(&g_n, trk[t] + 1);
}

// ---------------------------------------------------------------------------
// strip-major unranking (once per CTA). Strip r (128 rows): xx 64-col blocks
// u = 0..2(R-r)-1 (u<2 diag-mode, cblk = 2r+u), then nYb xy 64-col blocks.
// count(r) = 2(R-r) + nYb; cum(r) = r*(C1 - r), C1 = 2R + nYb + 1.
__device__ __forceinline__ void decode_t(int t, int C1, int R, int& r, int& u) {
    float b = (float)C1;
    float disc = b * b - 4.f * (float)t;
    int rr = (int)((b - sqrtf(disc)) * 0.5f);
    if (rr < 0) rr = 0;
    if (rr > R - 1) rr = R - 1;
    while (rr + 1 <= R - 1 && (rr + 1) * (C1 - (rr + 1)) <= t) rr++;
    while (rr > 0 && rr * (C1 - rr) > t) rr--;
    r = rr;
    u = t - rr * (C1 - rr);
}

__global__ void __launch_bounds__(256, 3)
k_gemm(const int* __restrict__ trk, int M, int nQ, float* __restrict__ out) {
    extern __shared__ char smem[];
    uint32_t gb = smem_u32(smem);
    int tid = threadIdx.x;
    int w = tid >> 5, lane = tid & 31;
    int n = g_n;

    int R = M / TILE;             // 64 row strips
    int nYb = nQ / NT;            // 64 xy col blocks
    int C1 = 2 * R + nYb + 1;     // 193
    int totTiles = R * (C1 - R);  // 8256
    int start = (int)(((long long)blockIdx.x * totTiles) / gridDim.x);
    int end   = (int)(((long long)(blockIdx.x + 1) * totTiles) / gridDim.x);

    float* rsS = (float*)(smem + GRS);   // [2][128]
    float* ssS = (float*)(smem + GSS);   // [2][128]
    if (tid < 128) {
        rsS[tid] = 0.f; rsS[128 + tid] = 0.f;
        ssS[tid] = 0.f; ssS[128 + tid] = 0.f;
    }

    int m0 = (w >> 1) * 32;       // 4 m-groups
    int n0 = (w & 1) * 32;        // 2 n-groups
    int slice = w & 1;
    int lrow = lane & 15;
    int lhalf = (lane >> 4) * 16;
    int q = lane >> 2, t4 = lane & 3;

#define LOAD_A(RR, AB) do {                                                     \
        uint32_t dstA_ = gb + ((AB) ? GA1 : GA0);                               \
        const uint8_t* asrc_ = g_xa + (size_t)(RR) * TILE * DK;                 \
        _Pragma("unroll")                                                       \
        for (int it = 0; it < 4; it++) {                                        \
            int c_ = tid + it * 256;                                            \
            int row_ = c_ >> 3, col_ = (c_ & 7) << 4;                           \
            cpasync16(dstA_ + row_ * ASTRB + col_, asrc_ + row_ * DK + col_);   \
        }                                                                       \
        if (tid < 32)                                                           \
            cpasync16(gb + GTRS + (AB) * 512 + tid * 16,                        \
                      trk + (RR) * TILE + tid * 4);                             \
    } while (0)

#define LOAD_B(RR, UU, BB) do {                                                 \
        uint32_t dstB_ = gb + ((BB) ? GB1 : GB0);                               \
        int nxx_ = 2 * (R - (RR));                                              \
        if ((UU) < nxx_) {                                                      \
            int cblk_ = 2 * (RR) + (UU);                                        \
            const uint8_t* bsrc_ = g_x8 + (size_t)cblk_ * NT * DK;              \
            _Pragma("unroll")                                                   \
            for (int it = 0; it < 2; it++) {                                    \
                int c_ = tid + it * 256;                                        \
                int row_ = c_ >> 3, col_ = (c_ & 7) << 4;                       \
                cpasync16(dstB_ + row_ * ASTRB + col_, bsrc_ + row_ * DK + col_);\
            }                                                                   \
            if (tid < 16)                                                       \
                cpasync16(gb + GTCS + (BB) * 256 + tid * 16,                    \
                          trk + cblk_ * NT + tid * 4);                          \
        } else {                                                                \
            int j_ = (UU) - nxx_;                                               \
            const uint8_t* bsrc_ = g_y8 + (size_t)j_ * NT * DK;                 \
            _Pragma("unroll")                                                   \
            for (int it = 0; it < 2; it++) {                                    \
                int c_ = tid + it * 256;                                        \
                int row_ = c_ >> 3, col_ = (c_ & 7) << 4;                       \
                cpasync16(dstB_ + row_ * ASTRB + col_, bsrc_ + row_ * DK + col_);\
            }                                                                   \
            if (tid < 64)                                                       \
                ((int*)(smem + GTCS + (BB) * 256))[tid] = (j_ * NT + tid) % n;  \
        }                                                                       \
    } while (0)

    // ---- prologue ----
    int rc, uc;
    decode_t(start, C1, R, rc, uc);
    int aBuf = 0, bBuf = 0;
    if (start < end) {
        LOAD_A(rc, 0);
        LOAD_B(rc, uc, 0);
    }
    asm volatile("cp.async.commit_group;" ::: "memory");

    for (int t = start; t < end; t++) {
        asm volatile("cp.async.wait_group 0;" ::: "memory");
        __syncthreads();

        // ---- next tile coords (incremental) ----
        bool haveNext = (t + 1 < end);
        int rn = rc, un = uc + 1;
        if (un == 2 * (R - rc) + nYb) { rn = rc + 1; un = 0; }
        bool aFlip = false;
        if (haveNext) {
            LOAD_B(rn, un, bBuf ^ 1);
            if (rn != rc) { LOAD_A(rn, aBuf ^ 1); aFlip = true; }
        }
        asm volatile("cp.async.commit_group;" ::: "memory");

        // ---- current tile flags ----
        bool isXY = (uc >= 2 * (R - rc));
        bool isDiag = (!isXY) && (uc < 2);
        const int* trC = (const int*)(smem + GTRS + aBuf * 512);
        const int* tcC = (const int*)(smem + GTCS + bBuf * 256);
        uint32_t aBase = gb + (aBuf ? GA1 : GA0);
        uint32_t bBase = gb + (bBuf ? GB1 : GB0);
        int dOff = uc * NT;           // diag: rloc == dOff + cl

        // ---- MMA: 32x32 warp tile ----
        uint32_t aAddr[2];
#pragma unroll
        for (int mi = 0; mi < 2; mi++)
            aAddr[mi] = aBase + (m0 + mi * 16 + lrow) * ASTRB + lhalf;
        uint32_t bAddr[2];
#pragma unroll
        for (int g2 = 0; g2 < 2; g2++)
            bAddr[g2] = bBase + (n0 + g2 * 16 + lrow) * ASTRB + lhalf;

        float acc[2][4][4];
#pragma unroll
        for (int mi = 0; mi < 2; mi++)
#pragma unroll
            for (int ni = 0; ni < 4; ni++)
#pragma unroll
                for (int e = 0; e < 4; e++) acc[mi][ni][e] = 0.f;

#pragma unroll
        for (int ks = 0; ks < 4; ks++) {
            uint32_t a[2][4], b[2][4];
#pragma unroll
            for (int mi = 0; mi < 2; mi++) ldmx4(a[mi], aAddr[mi] + ks * 32);
#pragma unroll
            for (int g2 = 0; g2 < 2; g2++) ldmx4(b[g2], bAddr[g2] + ks * 32);
#pragma unroll
            for (int mi = 0; mi < 2; mi++) {
                mma16832(acc[mi][0], a[mi], b[0][0], b[0][2]);
                mma16832(acc[mi][1], a[mi], b[0][1], b[0][3]);
                mma16832(acc[mi][2], a[mi], b[1][0], b[1][2]);
                mma16832(acc[mi][3], a[mi], b[1][1], b[1][3]);
            }
        }

        // ---- labels + warp-level no-match test ----
        int tcJ[8];
#pragma unroll
        for (int j = 0; j < 8; j++) {
            int ni = j >> 1, p = j & 1;
            tcJ[j] = tcC[n0 + ni * 8 + t4 * 2 + p];
        }
        int trv[4];
#pragma unroll
        for (int mi = 0; mi < 2; mi++) {
            trv[mi * 2]     = trC[m0 + mi * 16 + q];
            trv[mi * 2 + 1] = trC[m0 + mi * 16 + q + 8];
        }
        int cmin = tcJ[0], cmax = tcJ[0];
#pragma unroll
        for (int j = 1; j < 8; j++) { cmin = min(cmin, tcJ[j]); cmax = max(cmax, tcJ[j]); }
        int rmin = min(min(trv[0], trv[1]), min(trv[2], trv[3]));
        int rmax = max(max(trv[0], trv[1]), max(trv[2], trv[3]));
        bool poss = __any_sync(0xffffffffu, !(rmax < cmin || rmin > cmax));

        // ---- epilogue, specialized by tile mode + match possibility ----
#define EPI_CORE(DOS, DODIAG, DOCS, GM) do {                                    \
        float cs[4][2] = {{0.f,0.f},{0.f,0.f},{0.f,0.f},{0.f,0.f}};             \
        _Pragma("unroll")                                                       \
        for (int mi = 0; mi < 2; mi++) {                                        \
            _Pragma("unroll")                                                   \
            for (int h = 0; h < 2; h++) {                                       \
                int rloc = m0 + mi * 16 + q + h * 8;                            \
                int tr = trv[mi * 2 + h];                                       \
                float r_s = 0.f, s_s = 0.f;                                     \
                _Pragma("unroll")                                               \
                for (int ni = 0; ni < 4; ni++) {                                \
                    _Pragma("unroll")                                           \
                    for (int p = 0; p < 2; p++) {                               \
                        float e = ex2f(acc[mi][ni][h * 2 + p]);                 \
                        r_s += e;                                               \
                        if (DOS && tcJ[ni * 2 + p] == tr) s_s += e;             \
                        if (DODIAG &&                                           \
                            (dOff + n0 + ni * 8 + t4 * 2 + p == rloc))          \
                            atomicAdd(&g_DS[tr], (double)e);                    \
                        if (DOCS) cs[ni][p] += e;                               \
                    }                                                           \
                }                                                               \
                r_s += __shfl_xor_sync(0xffffffffu, r_s, 1);                    \
                r_s += __shfl_xor_sync(0xffffffffu, r_s, 2);                    \
                if (DOS) {                                                      \
                    s_s += __shfl_xor_sync(0xffffffffu, s_s, 1);                \
                    s_s += __shfl_xor_sync(0xffffffffu, s_s, 2);                \
                }                                                               \
                if (t4 == 0) {                                                  \
                    rsS[slice * 128 + rloc] += r_s;                             \
                    if (DOS) ssS[slice * 128 + rloc] += s_s * (GM);             \
                }                                                               \
            }                                                                   \
        }                                                                       \
        if (DOCS) {                                                             \
            _Pragma("unroll")                                                   \
            for (int ni = 0; ni < 4; ni++) {                                    \
                _Pragma("unroll")                                               \
                for (int p = 0; p < 2; p++) {                                   \
                    float v = cs[ni][p];                                        \
                    v += __shfl_xor_sync(0xffffffffu, v, 4);                    \
                    v += __shfl_xor_sync(0xffffffffu, v, 8);                    \
                    v += __shfl_xor_sync(0xffffffffu, v, 16);                   \
                    if (q == 0)                                                 \
                        atomicAdd(&g_RT[tcJ[ni * 2 + p]], (double)v);           \
                }                                                               \
            }                                                                   \
        }                                                                       \
    } while (0)

        if (isXY) {
            if (poss) EPI_CORE(true, false, false, 1.f);
            else      EPI_CORE(false, false, false, 1.f);
        } else if (isDiag) {
            EPI_CORE(true, true, false, 1.f);
        } else {
            if (poss) EPI_CORE(true, false, true, 2.f);
            else      EPI_CORE(false, false, true, 2.f);
        }
#undef EPI_CORE

        // ---- flush on strip/mode boundary ----
        bool nIsXY = haveNext && (un >= 2 * (R - rn));
        bool keep = haveNext && (rn == rc) && (nIsXY == isXY);
        if (!keep) {
            __syncthreads();
            if (tid < 128) {
                float rv = rsS[tid] + rsS[128 + tid];
                float sv = ssS[tid] + ssS[128 + tid];
                int tr = trC[tid];
                if (isXY) {
                    atomicAdd(&g_A[tr], (double)rv);
                    atomicAdd(&g_P[tr], (double)sv);
                } else {
                    atomicAdd(&g_RT[tr], (double)rv);
                    atomicAdd(&g_G[tr], (double)sv);
                }
                rsS[tid] = 0.f; rsS[128 + tid] = 0.f;
                ssS[tid] = 0.f; ssS[128 + tid] = 0.f;
            }
        }

        rc = rn; uc = un;
        bBuf ^= 1;
        if (aFlip) aBuf ^= 1;
    }
#undef LOAD_A
#undef LOAD_B

    // ---- in-kernel loss: last CTA to finish computes the scalar ----
    __syncthreads();
    __threadfence();
    __shared__ int sTicket;
    if (tid == 0) sTicket = atomicAdd(&g_done, 1);
    __syncthreads();
    if (sTicket == (int)gridDim.x - 1) {
        __shared__ double warpsum[8];
        int Q = nQ / n;
        double local = 0.0;
        for (int i = tid; i < n; i += 256) {
            double num = g_P[i] + 0.5 * (g_G[i] - g_DS[i]);
            double den = (g_A[i] - g_P[i]) + (g_RT[i] - g_G[i]);
            local += (double)logf((float)((num + den) / num));
        }
#pragma unroll
        for (int o = 16; o >= 1; o >>= 1)
            local += __shfl_xor_sync(0xffffffffu, local, o);
        if (lane == 0) warpsum[w] = local;
        __syncthreads();
        if (tid == 0) {
            double tt = 0.0;
            for (int i = 0; i < 8; i++) tt += warpsum[i];
            out[0] = (float)(tt / (double)n / (double)Q);
        }
    }
}

// ---------------------------------------------------------------------------
extern "C" void kernel_launch(void* const* d_in, const int* in_sizes, int n_in,
                              void* d_out, int out_size) {
    const float* x   = (const float*)d_in[0];
    const int*   trk = (const int*)d_in[1];
    const float* y   = (const float*)d_in[2];
    float* out = (float*)d_out;

    int M  = in_sizes[1];
    int D  = in_sizes[0] / M;
    int nQ = in_sizes[2] / D;

    cudaFuncSetAttribute(k_gemm, cudaFuncAttributeMaxDynamicSharedMemorySize, SM_TOTAL);

    int prepThreads = (M * D + nQ * D) / 4;
    if (prepThreads < MAX_M) prepThreads = MAX_M;
    k_prep<<<(prepThreads + 255) / 256, 256>>>(x, y, trk, M, nQ);

    k_gemm<<<NPCTA, 256, SM_TOTAL>>>(trk, M, nQ, out);
}

// round 16
// speedup vs baseline: 1.2281x; 1.2281x over previous
#include <cuda_runtime.h>
#include <math.h>
#include <stdint.h>

// ContrastiveLoss fused via warp-level FP8(e4m3) mma.sync (m16n8k32).
// Strip-major persistent CTAs (128x128 tiles, 2 CTAs/SM), A resident per
// strip (double-buffered), B double-buffered. Row sums live in REGISTERS
// across a run; shuffle-reduce + smem + global flush only at strip/mode
// boundaries. Strip-invariant row-label range for the no-match skip.
// In-kernel loss tail.
// Inputs: x [M,D] f32, track_idxs [M] i32, y [n,Q,D] f32. Output: scalar f32.

#define MAX_M  8192
#define DK     128
#define TILE   128
#define ASTRB  144            // padded row stride in bytes
#define NPCTA  296            // 2 per SM

// smem layout (bytes)
#define GA0    0              // A buf0 128x144
#define GA1    18432          // A buf1
#define GB0    36864          // B buf0
#define GB1    55296          // B buf1
#define GTRS   73728          // 2 x 512 row labels (paired with A bufs)
#define GTCS   74752          // 2 x 512 col labels (paired with B bufs)
#define GRS    75776          // 4 slices x 128 f32 row sums (boundary scratch)
#define GSS    77824          // 4 slices x 128 f32 same-track sums
#define SM_TOTAL 79872

__device__ uint8_t g_xa[(size_t)MAX_M * DK];       // x * log2(e)/T, e4m3 (A)
__device__ uint8_t g_x8[(size_t)MAX_M * DK];       // x, e4m3 (B, xx)
__device__ uint8_t g_y8[(size_t)MAX_M * DK / 2];   // y, e4m3 (B, xy)
__device__ double g_A[MAX_M];
__device__ double g_P[MAX_M];
__device__ double g_RT[MAX_M];
__device__ double g_G[MAX_M];
__device__ double g_DS[MAX_M];
__device__ int    g_n = 0;
__device__ int    g_done = 0;

__device__ __forceinline__ uint32_t smem_u32(const void* p) {
    uint32_t a;
    asm("{ .reg .u64 t; cvta.to.shared.u64 t, %1; cvt.u32.u64 %0, t; }" : "=r"(a) : "l"(p));
    return a;
}
__device__ __forceinline__ float ex2f(float x) {
    float r; asm("ex2.approx.f32 %0, %1;" : "=f"(r) : "f"(x)); return r;
}
__device__ __forceinline__ void ldmx4(uint32_t* r, uint32_t addr) {
    asm volatile("ldmatrix.sync.aligned.m8n8.x4.shared.b16 {%0,%1,%2,%3}, [%4];"
                 : "=r"(r[0]), "=r"(r[1]), "=r"(r[2]), "=r"(r[3]) : "r"(addr));
}
__device__ __forceinline__ void mma16832(float* d, const uint32_t* a, uint32_t b0, uint32_t b1) {
    asm volatile("mma.sync.aligned.m16n8k32.row.col.f32.e4m3.e4m3.f32 "
                 "{%0,%1,%2,%3}, {%4,%5,%6,%7}, {%8,%9}, {%0,%1,%2,%3};"
                 : "+f"(d[0]), "+f"(d[1]), "+f"(d[2]), "+f"(d[3])
                 : "r"(a[0]), "r"(a[1]), "r"(a[2]), "r"(a[3]), "r"(b0), "r"(b1));
}
__device__ __forceinline__ void cpasync16(uint32_t saddr, const void* gptr) {
    asm volatile("cp.async.cg.shared.global [%0], [%1], 16;" :: "r"(saddr), "l"(gptr));
}
__device__ __forceinline__ uint32_t pack_e4m3_4(float a, float b, float c, float d) {
    uint16_t lo, hi;
    asm("cvt.rn.satfinite.e4m3x2.f32 %0, %1, %2;" : "=h"(lo) : "f"(b), "f"(a));
    asm("cvt.rn.satfinite.e4m3x2.f32 %0, %1, %2;" : "=h"(hi) : "f"(d), "f"(c));
    return (uint32_t)lo | ((uint32_t)hi << 16);
}

// ---------------------------------------------------------------------------
__global__ void k_prep(const float* __restrict__ x, const float* __restrict__ y,
                       const int* __restrict__ trk, int M, int nQ) {
    const float S = 1.4426950408889634f / 0.3f;   // log2(e)/TEMP
    int t = blockIdx.x * blockDim.x + threadIdx.x;
    int nx4 = M * DK / 4;
    int ny4 = nQ * DK / 4;
    if (t < nx4) {
        float4 v = *reinterpret_cast<const float4*>(x + t * 4);
        *reinterpret_cast<uint32_t*>(g_xa + t * 4) =
            pack_e4m3_4(v.x * S, v.y * S, v.z * S, v.w * S);
        *reinterpret_cast<uint32_t*>(g_x8 + t * 4) = pack_e4m3_4(v.x, v.y, v.z, v.w);
    } else if (t < nx4 + ny4) {
        int i = t - nx4;
        float4 v = *reinterpret_cast<const float4*>(y + i * 4);
        *reinterpret_cast<uint32_t*>(g_y8 + i * 4) = pack_e4m3_4(v.x, v.y, v.z, v.w);
    }
    if (t < MAX_M) { g_A[t] = 0; g_P[t] = 0; g_RT[t] = 0; g_G[t] = 0; g_DS[t] = 0; }
    if (t == 0) g_done = 0;
    if (t < M) atomicMax(&g_n, trk[t] + 1);
}

// ---------------------------------------------------------------------------
// strip-major unranking (once per CTA). Strip r: xx col-blocks u=0..nXX-r-1
// (u==0 diag), then nYc xy blocks. cum(r) = C*r - r(r-1)/2, C = nXX + nYc.
__device__ __forceinline__ void decode_t(int t, int C, int nXX, int& r, int& u) {
    float b = 2.f * C + 1.f;
    float disc = b * b - 8.f * (float)t;
    int rr = (int)((b - sqrtf(disc)) * 0.5f);
    if (rr < 0) rr = 0;
    if (rr > nXX - 1) rr = nXX - 1;
    while (rr + 1 <= nXX - 1 && (rr + 1) * C - ((rr + 1) * rr) / 2 <= t) rr++;
    while (rr > 0 && rr * C - (rr * (rr - 1)) / 2 > t) rr--;
    r = rr;
    u = t - (rr * C - (rr * (rr - 1)) / 2);
}

__global__ void __launch_bounds__(256, 2)
k_gemm(const int* __restrict__ trk, int M, int nQ, float* __restrict__ out) {
    extern __shared__ char smem[];
    uint32_t gb = smem_u32(smem);
    int tid = threadIdx.x;
    int w = tid >> 5, lane = tid & 31;
    int n = g_n;

    int nXX = M / TILE;           // 64
    int nYc = nQ / TILE;          // 32
    int C = nXX + nYc;            // 96
    int totTiles = nXX * C - (nXX * (nXX - 1)) / 2;   // 4128
    int start = (int)(((long long)blockIdx.x * totTiles) / gridDim.x);
    int end   = (int)(((long long)(blockIdx.x + 1) * totTiles) / gridDim.x);

    float* rsS = (float*)(smem + GRS);   // [4][128] boundary scratch
    float* ssS = (float*)(smem + GSS);   // [4][128]

    int m0 = (w >> 2) * 64;
    int n0 = (w & 3) * 32;
    int slice = w & 3;
    int lrow = lane & 15;
    int lhalf = (lane >> 4) * 16;
    int q = lane >> 2, t4 = lane & 3;

    // register row accumulators (persist across a run)
    float racc[4][2], sacc[4][2];
#pragma unroll
    for (int mi = 0; mi < 4; mi++) { racc[mi][0] = racc[mi][1] = 0.f;
                                     sacc[mi][0] = sacc[mi][1] = 0.f; }

#define LOAD_A(RR, AB) do {                                                     \
        uint32_t dstA_ = gb + ((AB) ? GA1 : GA0);                               \
        const uint8_t* asrc_ = g_xa + (size_t)(RR) * TILE * DK;                 \
        _Pragma("unroll")                                                       \
        for (int it = 0; it < 4; it++) {                                        \
            int c_ = tid + it * 256;                                            \
            int row_ = c_ >> 3, col_ = (c_ & 7) << 4;                           \
            cpasync16(dstA_ + row_ * ASTRB + col_, asrc_ + row_ * DK + col_);   \
        }                                                                       \
        if (tid < 32)                                                           \
            cpasync16(gb + GTRS + (AB) * 512 + tid * 16,                        \
                      trk + (RR) * TILE + tid * 4);                             \
    } while (0)

#define LOAD_B(RR, UU, BB) do {                                                 \
        uint32_t dstB_ = gb + ((BB) ? GB1 : GB0);                               \
        int nxx_ = nXX - (RR);                                                  \
        if ((UU) < nxx_) {                                                      \
            int cblk_ = (RR) + (UU);                                            \
            const uint8_t* bsrc_ = g_x8 + (size_t)cblk_ * TILE * DK;            \
            _Pragma("unroll")                                                   \
            for (int it = 0; it < 4; it++) {                                    \
                int c_ = tid + it * 256;                                        \
                int row_ = c_ >> 3, col_ = (c_ & 7) << 4;                       \
                cpasync16(dstB_ + row_ * ASTRB + col_, bsrc_ + row_ * DK + col_);\
            }                                                                   \
            if (tid < 32)                                                       \
                cpasync16(gb + GTCS + (BB) * 512 + tid * 16,                    \
                          trk + cblk_ * TILE + tid * 4);                        \
        } else {                                                                \
            int j_ = (UU) - nxx_;                                               \
            const uint8_t* bsrc_ = g_y8 + (size_t)j_ * TILE * DK;               \
            _Pragma("unroll")                                                   \
            for (int it = 0; it < 4; it++) {                                    \
                int c_ = tid + it * 256;                                        \
                int row_ = c_ >> 3, col_ = (c_ & 7) << 4;                       \
                cpasync16(dstB_ + row_ * ASTRB + col_, bsrc_ + row_ * DK + col_);\
            }                                                                   \
            if (tid < 128)                                                      \
                ((int*)(smem + GTCS + (BB) * 512))[tid] = (j_ * TILE + tid) % n;\
        }                                                                       \
    } while (0)

    // ---- prologue ----
    int rc, uc;
    decode_t(start, C, nXX, rc, uc);
    int aBuf = 0, bBuf = 0;
    if (start < end) {
        LOAD_A(rc, 0);
        LOAD_B(rc, uc, 0);
    }
    asm volatile("cp.async.commit_group;" ::: "memory");

    bool newStrip = true;
    int rmin = 0, rmax = 0;

    for (int t = start; t < end; t++) {
        asm volatile("cp.async.wait_group 0;" ::: "memory");
        __syncthreads();

        // ---- next tile coords (incremental) ----
        bool haveNext = (t + 1 < end);
        int rn = rc, un = uc + 1;
        if (un == (nXX - rc) + nYc) { rn = rc + 1; un = 0; }
        bool aFlip = false;
        if (haveNext) {
            LOAD_B(rn, un, bBuf ^ 1);
            if (rn != rc) { LOAD_A(rn, aBuf ^ 1); aFlip = true; }
        }
        asm volatile("cp.async.commit_group;" ::: "memory");

        // ---- current tile flags ----
        bool isXY = (uc >= nXX - rc);
        bool isDiag = (uc == 0);
        const int* trC = (const int*)(smem + GTRS + aBuf * 512);
        const int* tcC = (const int*)(smem + GTCS + bBuf * 512);
        uint32_t aBase = gb + (aBuf ? GA1 : GA0);
        uint32_t bBase = gb + (bBuf ? GB1 : GB0);

        // strip-invariant row label range (for skip test)
        if (newStrip) {
            int v0 = trC[m0 + q], v1 = trC[m0 + q + 8];
            rmin = min(v0, v1); rmax = max(v0, v1);
#pragma unroll
            for (int mi = 1; mi < 4; mi++) {
                int a0 = trC[m0 + mi * 16 + q], a1 = trC[m0 + mi * 16 + q + 8];
                rmin = min(rmin, min(a0, a1));
                rmax = max(rmax, max(a0, a1));
            }
            newStrip = false;
        }

        // ---- MMA ----
        uint32_t aAddr[4];
#pragma unroll
        for (int mi = 0; mi < 4; mi++)
            aAddr[mi] = aBase + (m0 + mi * 16 + lrow) * ASTRB + lhalf;
        uint32_t bAddr[2];
#pragma unroll
        for (int g2 = 0; g2 < 2; g2++)
            bAddr[g2] = bBase + (n0 + g2 * 16 + lrow) * ASTRB + lhalf;

        float acc[4][4][4];
#pragma unroll
        for (int mi = 0; mi < 4; mi++)
#pragma unroll
            for (int ni = 0; ni < 4; ni++)
#pragma unroll
                for (int e = 0; e < 4; e++) acc[mi][ni][e] = 0.f;

#pragma unroll
        for (int ks = 0; ks < 4; ks++) {
            uint32_t a[4][4], b[2][4];
#pragma unroll
            for (int mi = 0; mi < 4; mi++) ldmx4(a[mi], aAddr[mi] + ks * 32);
#pragma unroll
            for (int g2 = 0; g2 < 2; g2++) ldmx4(b[g2], bAddr[g2] + ks * 32);
#pragma unroll
            for (int mi = 0; mi < 4; mi++) {
                mma16832(acc[mi][0], a[mi], b[0][0], b[0][2]);
                mma16832(acc[mi][1], a[mi], b[0][1], b[0][3]);
                mma16832(acc[mi][2], a[mi], b[1][0], b[1][2]);
                mma16832(acc[mi][3], a[mi], b[1][1], b[1][3]);
            }
        }

        // ---- col labels + warp-level no-match test ----
        int tcJ[8];
#pragma unroll
        for (int j = 0; j < 8; j++) {
            int ni = j >> 1, p = j & 1;
            tcJ[j] = tcC[n0 + ni * 8 + t4 * 2 + p];
        }
        int cmin = tcJ[0], cmax = tcJ[0];
#pragma unroll
        for (int j = 1; j < 8; j++) { cmin = min(cmin, tcJ[j]); cmax = max(cmax, tcJ[j]); }
        bool poss = __any_sync(0xffffffffu, !(rmax < cmin || rmin > cmax));

        // ---- epilogue: exp + per-thread partials into register accumulators ----
#define EPI_CORE(DOS, DODIAG, DOCS, GM) do {                                    \
        float cs[4][2] = {{0.f,0.f},{0.f,0.f},{0.f,0.f},{0.f,0.f}};             \
        _Pragma("unroll")                                                       \
        for (int mi = 0; mi < 4; mi++) {                                        \
            _Pragma("unroll")                                                   \
            for (int h = 0; h < 2; h++) {                                       \
                int rloc = m0 + mi * 16 + q + h * 8;                            \
                int tr = trC[rloc];                                             \
                float r_s = 0.f, s_s = 0.f;                                     \
                _Pragma("unroll")                                               \
                for (int ni = 0; ni < 4; ni++) {                                \
                    _Pragma("unroll")                                           \
                    for (int p = 0; p < 2; p++) {                               \
                        float e = ex2f(acc[mi][ni][h * 2 + p]);                 \
                        r_s += e;                                               \
                        if (DOS && tcJ[ni * 2 + p] == tr) s_s += e;             \
                        if (DODIAG && (n0 + ni * 8 + t4 * 2 + p == rloc))       \
                            atomicAdd(&g_DS[tr], (double)e);                    \
                        if (DOCS) cs[ni][p] += e;                               \
                    }                                                           \
                }                                                               \
                racc[mi][h] += r_s;                                             \
                if (DOS) sacc[mi][h] = fmaf(s_s, (GM), sacc[mi][h]);            \
            }                                                                   \
        }                                                                       \
        if (DOCS) {                                                             \
            _Pragma("unroll")                                                   \
            for (int ni = 0; ni < 4; ni++) {                                    \
                _Pragma("unroll")                                               \
                for (int p = 0; p < 2; p++) {                                   \
                    float v = cs[ni][p];                                        \
                    v += __shfl_xor_sync(0xffffffffu, v, 4);                    \
                    v += __shfl_xor_sync(0xffffffffu, v, 8);                    \
                    v += __shfl_xor_sync(0xffffffffu, v, 16);                   \
                    if (q == 0)                                                 \
                        atomicAdd(&g_RT[tcJ[ni * 2 + p]], (double)v);           \
                }                                                               \
            }                                                                   \
        }                                                                       \
    } while (0)

        if (isXY) {
            if (poss) EPI_CORE(true, false, false, 1.f);
            else      EPI_CORE(false, false, false, 1.f);
        } else if (isDiag) {
            EPI_CORE(true, true, false, 1.f);
        } else {
            if (poss) EPI_CORE(true, false, true, 2.f);
            else      EPI_CORE(false, false, true, 2.f);
        }
#undef EPI_CORE

        // ---- flush on strip/mode boundary: reduce register accumulators ----
        bool nIsXY = haveNext && (un >= nXX - rn);
        bool keep = haveNext && (rn == rc) && (nIsXY == isXY);
        if (!keep) {
#pragma unroll
            for (int mi = 0; mi < 4; mi++) {
#pragma unroll
                for (int h = 0; h < 2; h++) {
                    float v = racc[mi][h];
                    v += __shfl_xor_sync(0xffffffffu, v, 1);
                    v += __shfl_xor_sync(0xffffffffu, v, 2);
                    float s = sacc[mi][h];
                    s += __shfl_xor_sync(0xffffffffu, s, 1);
                    s += __shfl_xor_sync(0xffffffffu, s, 2);
                    if (t4 == 0) {
                        int rloc = m0 + mi * 16 + q + h * 8;
                        rsS[slice * 128 + rloc] = v;
                        ssS[slice * 128 + rloc] = s;
                    }
                    racc[mi][h] = 0.f;
                    sacc[mi][h] = 0.f;
                }
            }
            __syncthreads();
            if (tid < 128) {
                float rv = rsS[tid] + rsS[128 + tid] + rsS[256 + tid] + rsS[384 + tid];
                float sv = ssS[tid] + ssS[128 + tid] + ssS[256 + tid] + ssS[384 + tid];
                int tr = trC[tid];
                if (isXY) {
                    atomicAdd(&g_A[tr], (double)rv);
                    atomicAdd(&g_P[tr], (double)sv);
                } else {
                    atomicAdd(&g_RT[tr], (double)rv);
                    atomicAdd(&g_G[tr], (double)sv);
                }
            }
        }

        rc = rn; uc = un;
        bBuf ^= 1;
        if (aFlip) { aBuf ^= 1; newStrip = true; }
    }
#undef LOAD_A
#undef LOAD_B

    // ---- in-kernel loss: last CTA to finish computes the scalar ----
    __syncthreads();
    __threadfence();
    __shared__ int sTicket;
    if (tid == 0) sTicket = atomicAdd(&g_done, 1);
    __syncthreads();
    if (sTicket == (int)gridDim.x - 1) {
        __shared__ double warpsum[8];
        int Q = nQ / n;
        double local = 0.0;
        for (int i = tid; i < n; i += 256) {
            double num = g_P[i] + 0.5 * (g_G[i] - g_DS[i]);
            double den = (g_A[i] - g_P[i]) + (g_RT[i] - g_G[i]);
            local += (double)logf((float)((num + den) / num));
        }
#pragma unroll
        for (int o = 16; o >= 1; o >>= 1)
            local += __shfl_xor_sync(0xffffffffu, local, o);
        if (lane == 0) warpsum[w] = local;
        __syncthreads();
        if (tid == 0) {
            double tt = 0.0;
            for (int i = 0; i < 8; i++) tt += warpsum[i];
            out[0] = (float)(tt / (double)n / (double)Q);
        }
    }
}

// ---------------------------------------------------------------------------
extern "C" void kernel_launch(void* const* d_in, const int* in_sizes, int n_in,
                              void* d_out, int out_size) {
    const float* x   = (const float*)d_in[0];
    const int*   trk = (const int*)d_in[1];
    const float* y   = (const float*)d_in[2];
    float* out = (float*)d_out;

    int M  = in_sizes[1];
    int D  = in_sizes[0] / M;
    int nQ = in_sizes[2] / D;

    cudaFuncSetAttribute(k_gemm, cudaFuncAttributeMaxDynamicSharedMemorySize, SM_TOTAL);

    int prepThreads = (M * D + nQ * D) / 4;
    if (prepThreads < MAX_M) prepThreads = MAX_M;
    k_prep<<<(prepThreads + 255) / 256, 256>>>(x, y, trk, M, nQ);

    k_gemm<<<NPCTA, 256, SM_TOTAL>>>(trk, M, nQ, out);
}